// round 2
// baseline (speedup 1.0000x reference)
#include <cuda_runtime.h>

#define B_  8
#define N_  8192
#define M_  2048
#define C_  64
#define K_  32
#define CH_ 67     // 3 coords + 64 features
#define ROWW 68    // padded row width in transposed layout

// Scratch (device globals — no allocation allowed)
__device__ float g_ptsT[B_ * N_ * ROWW];   // [b][n][68] : x,y,z,f0..f63,pad  (~17.8 MB)
__device__ int   g_idx[B_ * M_ * K_];      // [b][m][32] selected neighbor indices (2 MB)

// ---------------------------------------------------------------------------
// Kernel A: pack + transpose (B,3,N)+(B,64,N) -> ptsT[b][n][67(+1)]
// ---------------------------------------------------------------------------
__global__ void __launch_bounds__(256) transpose_k(const float* __restrict__ pc,
                                                   const float* __restrict__ feat) {
    __shared__ float tile[CH_][33];
    int b  = blockIdx.y;
    int n0 = blockIdx.x * 32;
    int tx = threadIdx.x;   // 0..31
    int ty = threadIdx.y;   // 0..7

    for (int ch = ty; ch < CH_; ch += 8) {
        float v = (ch < 3)
            ? pc[((size_t)(b * 3 + ch)) * N_ + n0 + tx]
            : feat[((size_t)(b * C_ + (ch - 3))) * N_ + n0 + tx];
        tile[ch][tx] = v;
    }
    __syncthreads();

    for (int r = ty; r < 32; r += 8) {
        float* row = g_ptsT + (size_t)(b * N_ + n0 + r) * ROWW;
        row[tx]      = tile[tx][r];
        row[32 + tx] = tile[32 + tx][r];
        if (tx < 3) row[64 + tx] = tile[64 + tx][r];
    }
}

// ---------------------------------------------------------------------------
// Kernel B: ball query. One warp per center; point coords + |p|^2 staged in
// shared. Replicates reference numerics EXACTLY:
//   p2, c2: rn-mul + rn-add chain (XLA elementwise reduce, no contraction)
//   dot:    cuBLAS K=3 FMA chain  fma(c2,p2, fma(c1,p1, c0*p0))
//   d2 = (c2 + p2) - (dot + dot),  hit = d2 < 0.01f
// Ordered first-32 selection via ballot + prefix-popc; early exit at 32 hits.
// ---------------------------------------------------------------------------
#define WARPS_B 16
__global__ void __launch_bounds__(32 * WARPS_B, 1)
ballquery_k(const float* __restrict__ pc, const float* __restrict__ cc) {
    extern __shared__ float sm[];
    float* xs = sm;
    float* ys = sm + N_;
    float* zs = sm + 2 * N_;
    float* q2 = sm + 3 * N_;
    int*  bufs = (int*)(sm + 4 * N_);   // WARPS_B * 64 ints

    int b = blockIdx.y;
    const float* src = pc + (size_t)b * 3 * N_;
    for (int i = threadIdx.x; i < 3 * N_; i += 32 * WARPS_B) sm[i] = src[i];
    __syncthreads();
    for (int i = threadIdx.x; i < N_; i += 32 * WARPS_B) {
        float x = xs[i], y = ys[i], z = zs[i];
        q2[i] = __fadd_rn(__fadd_rn(__fmul_rn(x, x), __fmul_rn(y, y)), __fmul_rn(z, z));
    }
    __syncthreads();

    int warp = threadIdx.x >> 5;
    int lane = threadIdx.x & 31;
    int m = blockIdx.x * WARPS_B + warp;
    int* buf = bufs + warp * 64;

    float cx = cc[(size_t)(b * 3 + 0) * M_ + m];
    float cy = cc[(size_t)(b * 3 + 1) * M_ + m];
    float cz = cc[(size_t)(b * 3 + 2) * M_ + m];
    float c2 = __fadd_rn(__fadd_rn(__fmul_rn(cx, cx), __fmul_rn(cy, cy)), __fmul_rn(cz, cz));
    const float R2 = 0.01f;

    int cnt = 0;
    for (int s = 0; s < N_; s += 32) {
        int i = s + lane;
        float px = xs[i], py = ys[i], pz = zs[i], q = q2[i];
        // cuBLAS-style K=3 FMA chain (k ascending)
        float dot = __fmaf_rn(cz, pz, __fmaf_rn(cy, py, __fmul_rn(cx, px)));
        float d2  = __fsub_rn(__fadd_rn(c2, q), __fadd_rn(dot, dot));
        bool hit = d2 < R2;
        unsigned mask = __ballot_sync(0xffffffffu, hit);
        if (hit) {
            int pos = cnt + __popc(mask & ((1u << lane) - 1u));
            if (pos < K_) buf[pos] = i;
        }
        cnt += __popc(mask);
        if (cnt >= K_) break;
    }
    __syncwarp();

    int out_i;
    if (cnt == 0) {
        out_i = 0;
    } else {
        int first = buf[0];
        out_i = (lane < cnt) ? buf[lane] : first;
    }
    g_idx[((size_t)b * M_ + m) * K_ + lane] = out_i;
}

// ---------------------------------------------------------------------------
// Kernel C: gather. One warp per center. Coalesced row reads from ptsT,
// per-warp shared transpose, coalesced 128B output stores.
// ---------------------------------------------------------------------------
#define WARPS_C 8
__global__ void __launch_bounds__(32 * WARPS_C)
gather_k(const float* __restrict__ cc, float* __restrict__ out) {
    extern __shared__ float smc[];   // WARPS_C tiles of [CH_][33]
    int b    = blockIdx.y;
    int warp = threadIdx.x >> 5;
    int lane = threadIdx.x & 31;
    int m = blockIdx.x * WARPS_C + warp;
    float* tile = smc + warp * (CH_ * 33);

    int my_i = g_idx[((size_t)b * M_ + m) * K_ + lane];

    #pragma unroll 8
    for (int j = 0; j < K_; j++) {
        int ij = __shfl_sync(0xffffffffu, my_i, j);
        const float* row = g_ptsT + (size_t)(b * N_ + ij) * ROWW;
        float v0 = row[lane];
        float v1 = row[32 + lane];
        tile[lane * 33 + j]        = v0;
        tile[(32 + lane) * 33 + j] = v1;
        if (lane < 3) tile[(64 + lane) * 33 + j] = row[64 + lane];
    }
    __syncwarp();

    float cx = cc[(size_t)(b * 3 + 0) * M_ + m];
    float cy = cc[(size_t)(b * 3 + 1) * M_ + m];
    float cz = cc[(size_t)(b * 3 + 2) * M_ + m];

    size_t obase = (((size_t)b * CH_) * M_ + m) * K_ + lane;
    const size_t cstride = (size_t)M_ * K_;
    out[obase + 0 * cstride] = __fsub_rn(tile[0 * 33 + lane], cx);
    out[obase + 1 * cstride] = __fsub_rn(tile[1 * 33 + lane], cy);
    out[obase + 2 * cstride] = __fsub_rn(tile[2 * 33 + lane], cz);
    #pragma unroll
    for (int c = 3; c < CH_; c++) {
        out[obase + (size_t)c * cstride] = tile[c * 33 + lane];
    }
}

// ---------------------------------------------------------------------------
extern "C" void kernel_launch(void* const* d_in, const int* in_sizes, int n_in,
                              void* d_out, int out_size) {
    const float* points_coords  = (const float*)d_in[0];   // (8, 3, 8192)
    const float* centers_coords = (const float*)d_in[1];   // (8, 3, 2048)
    const float* points_feats   = (const float*)d_in[2];   // (8, 64, 8192)
    float* out = (float*)d_out;                            // (8, 67, 2048, 32)

    static bool attr_done = false;
    if (!attr_done) {
        cudaFuncSetAttribute(ballquery_k, cudaFuncAttributeMaxDynamicSharedMemorySize,
                             (4 * N_) * (int)sizeof(float) + WARPS_B * 64 * (int)sizeof(int));
        cudaFuncSetAttribute(gather_k, cudaFuncAttributeMaxDynamicSharedMemorySize,
                             WARPS_C * CH_ * 33 * (int)sizeof(float));
        attr_done = true;
    }

    // A: transpose/pack
    {
        dim3 grid(N_ / 32, B_);
        dim3 block(32, 8);
        transpose_k<<<grid, block>>>(points_coords, points_feats);
    }
    // B: ball query
    {
        dim3 grid(M_ / WARPS_B, B_);
        size_t smem = (4 * N_) * sizeof(float) + WARPS_B * 64 * sizeof(int);
        ballquery_k<<<grid, 32 * WARPS_B, smem>>>(points_coords, centers_coords);
    }
    // C: gather + write
    {
        dim3 grid(M_ / WARPS_C, B_);
        size_t smem = WARPS_C * CH_ * 33 * sizeof(float);
        gather_k<<<grid, 32 * WARPS_C, smem>>>(centers_coords, out);
    }
}

// round 3
// speedup vs baseline: 1.4990x; 1.4990x over previous
#include <cuda_runtime.h>

#define B_  8
#define N_  8192
#define M_  2048
#define C_  64
#define K_  32
#define CH_ 67     // 3 coords + 64 features
#define ROWW 68    // padded row width in transposed layout

// Scratch (device globals — no allocation allowed)
__device__ float g_ptsT[B_ * N_ * ROWW];   // [b][n][68] : x,y,z,f0..f63,pad
__device__ int   g_idx[B_ * M_ * K_];      // [b][m][32]

// ---------------------------------------------------------------------------
// Kernel A: pack + transpose (B,3,N)+(B,64,N) -> ptsT[b][n][67(+1)]
// ---------------------------------------------------------------------------
__global__ void __launch_bounds__(256) transpose_k(const float* __restrict__ pc,
                                                   const float* __restrict__ feat) {
    __shared__ float tile[CH_][33];
    int b  = blockIdx.y;
    int n0 = blockIdx.x * 32;
    int tx = threadIdx.x;   // 0..31
    int ty = threadIdx.y;   // 0..7

    for (int ch = ty; ch < CH_; ch += 8) {
        float v = (ch < 3)
            ? pc[((size_t)(b * 3 + ch)) * N_ + n0 + tx]
            : feat[((size_t)(b * C_ + (ch - 3))) * N_ + n0 + tx];
        tile[ch][tx] = v;
    }
    __syncthreads();

    for (int r = ty; r < 32; r += 8) {
        float* row = g_ptsT + (size_t)(b * N_ + n0 + r) * ROWW;
        row[tx]      = tile[tx][r];
        row[32 + tx] = tile[32 + tx][r];
        if (tx < 3) row[64 + tx] = tile[64 + tx][r];
    }
}

// ---------------------------------------------------------------------------
// Kernel B: ball query. 4 centers per warp (register-blocked), point coords
// staged in shared, q^2 recomputed per iteration (bit-identical rn chain,
// amortized over 4 centers). Numerics identical to the passing R2 kernel:
//   q2, c2: rn mul/add chain;  dot: fma(cz,pz, fma(cy,py, cx*px))
//   d2 = (c2 + q) - (dot + dot);  hit = d2 < 0.01f
// ---------------------------------------------------------------------------
#define WARPS_B 16
#define CPW     4                      // centers per warp
#define TPB_B   (32 * WARPS_B)         // 512 threads
#define CPB     (WARPS_B * CPW)        // 64 centers per CTA

__global__ void __launch_bounds__(TPB_B, 2)
ballquery_k(const float* __restrict__ pc, const float* __restrict__ cc) {
    extern __shared__ float sm[];
    float* xs = sm;
    float* ys = sm + N_;
    float* zs = sm + 2 * N_;
    int*  bufs = (int*)(sm + 3 * N_);  // [WARPS_B][CPW][K_]

    int b = blockIdx.y;
    const float* src = pc + (size_t)b * 3 * N_;
    for (int i = threadIdx.x; i < N_; i += TPB_B) {
        xs[i] = src[i];
        ys[i] = src[N_ + i];
        zs[i] = src[2 * N_ + i];
    }
    __syncthreads();

    int warp = threadIdx.x >> 5;
    int lane = threadIdx.x & 31;
    unsigned lmask_lt = (1u << lane) - 1u;
    int m0 = blockIdx.x * CPB + warp * CPW;
    int* buf = bufs + (warp * CPW) * K_;

    float cx[CPW], cy[CPW], cz[CPW], c2[CPW];
    int cnt[CPW];
    #pragma unroll
    for (int c = 0; c < CPW; c++) {
        int m = m0 + c;
        cx[c] = cc[(size_t)(b * 3 + 0) * M_ + m];
        cy[c] = cc[(size_t)(b * 3 + 1) * M_ + m];
        cz[c] = cc[(size_t)(b * 3 + 2) * M_ + m];
        c2[c] = __fadd_rn(__fadd_rn(__fmul_rn(cx[c], cx[c]), __fmul_rn(cy[c], cy[c])),
                          __fmul_rn(cz[c], cz[c]));
        cnt[c] = 0;
    }
    const float R2 = 0.01f;

    for (int s = 0; s < N_; s += 32) {
        int i = s + lane;
        float px = xs[i], py = ys[i], pz = zs[i];
        float q = __fadd_rn(__fadd_rn(__fmul_rn(px, px), __fmul_rn(py, py)),
                            __fmul_rn(pz, pz));
        #pragma unroll
        for (int c = 0; c < CPW; c++) {
            float dot = __fmaf_rn(cz[c], pz, __fmaf_rn(cy[c], py, __fmul_rn(cx[c], px)));
            float d2  = __fsub_rn(__fadd_rn(c2[c], q), __fadd_rn(dot, dot));
            bool hit = d2 < R2;
            unsigned mask = __ballot_sync(0xffffffffu, hit);
            if (hit) {
                int pos = cnt[c] + __popc(mask & lmask_lt);
                if (pos < K_) buf[c * K_ + pos] = i;
            }
            cnt[c] += __popc(mask);
        }
        if ((cnt[0] >= K_) & (cnt[1] >= K_) & (cnt[2] >= K_) & (cnt[3] >= K_)) break;
    }
    __syncwarp();

    #pragma unroll
    for (int c = 0; c < CPW; c++) {
        int cn = cnt[c];
        int out_i;
        if (cn == 0) {
            out_i = 0;
        } else {
            int first = buf[c * K_ + 0];
            out_i = (lane < cn) ? buf[c * K_ + lane] : first;
        }
        g_idx[((size_t)b * M_ + m0 + c) * K_ + lane] = out_i;
    }
}

// ---------------------------------------------------------------------------
// Kernel C: gather. One warp per center. Coalesced row reads from ptsT,
// per-warp shared transpose, coalesced 128B output stores.
// ---------------------------------------------------------------------------
#define WARPS_C 8
__global__ void __launch_bounds__(32 * WARPS_C)
gather_k(const float* __restrict__ cc, float* __restrict__ out) {
    extern __shared__ float smc[];   // WARPS_C tiles of [CH_][33]
    int b    = blockIdx.y;
    int warp = threadIdx.x >> 5;
    int lane = threadIdx.x & 31;
    int m = blockIdx.x * WARPS_C + warp;
    float* tile = smc + warp * (CH_ * 33);

    int my_i = g_idx[((size_t)b * M_ + m) * K_ + lane];

    #pragma unroll 8
    for (int j = 0; j < K_; j++) {
        int ij = __shfl_sync(0xffffffffu, my_i, j);
        const float* row = g_ptsT + (size_t)(b * N_ + ij) * ROWW;
        float v0 = row[lane];
        float v1 = row[32 + lane];
        tile[lane * 33 + j]        = v0;
        tile[(32 + lane) * 33 + j] = v1;
        if (lane < 3) tile[(64 + lane) * 33 + j] = row[64 + lane];
    }
    __syncwarp();

    float cx = cc[(size_t)(b * 3 + 0) * M_ + m];
    float cy = cc[(size_t)(b * 3 + 1) * M_ + m];
    float cz = cc[(size_t)(b * 3 + 2) * M_ + m];

    size_t obase = (((size_t)b * CH_) * M_ + m) * K_ + lane;
    const size_t cstride = (size_t)M_ * K_;
    out[obase + 0 * cstride] = __fsub_rn(tile[0 * 33 + lane], cx);
    out[obase + 1 * cstride] = __fsub_rn(tile[1 * 33 + lane], cy);
    out[obase + 2 * cstride] = __fsub_rn(tile[2 * 33 + lane], cz);
    #pragma unroll
    for (int c = 3; c < CH_; c++) {
        out[obase + (size_t)c * cstride] = tile[c * 33 + lane];
    }
}

// ---------------------------------------------------------------------------
extern "C" void kernel_launch(void* const* d_in, const int* in_sizes, int n_in,
                              void* d_out, int out_size) {
    const float* points_coords  = (const float*)d_in[0];   // (8, 3, 8192)
    const float* centers_coords = (const float*)d_in[1];   // (8, 3, 2048)
    const float* points_feats   = (const float*)d_in[2];   // (8, 64, 8192)
    float* out = (float*)d_out;                            // (8, 67, 2048, 32)

    const int smem_bq = 3 * N_ * (int)sizeof(float) + WARPS_B * CPW * K_ * (int)sizeof(int);
    const int smem_g  = WARPS_C * CH_ * 33 * (int)sizeof(float);

    static bool init_done = false;
    static cudaStream_t s1;
    static cudaEvent_t e_fork, e_join;
    if (!init_done) {
        cudaFuncSetAttribute(ballquery_k, cudaFuncAttributeMaxDynamicSharedMemorySize, smem_bq);
        cudaFuncSetAttribute(gather_k, cudaFuncAttributeMaxDynamicSharedMemorySize, smem_g);
        cudaStreamCreateWithFlags(&s1, cudaStreamNonBlocking);
        cudaEventCreateWithFlags(&e_fork, cudaEventDisableTiming);
        cudaEventCreateWithFlags(&e_join, cudaEventDisableTiming);
        init_done = true;
    }

    cudaStream_t s0 = 0;  // capture/default stream

    // Fork: transpose on s1, ballquery on s0 (independent of each other)
    cudaEventRecord(e_fork, s0);
    cudaStreamWaitEvent(s1, e_fork, 0);

    {
        dim3 grid(N_ / 32, B_);
        dim3 block(32, 8);
        transpose_k<<<grid, block, 0, s1>>>(points_coords, points_feats);
    }
    {
        dim3 grid(M_ / CPB, B_);
        ballquery_k<<<grid, TPB_B, smem_bq, s0>>>(points_coords, centers_coords);
    }

    // Join: gather needs both g_ptsT (s1) and g_idx (s0)
    cudaEventRecord(e_join, s1);
    cudaStreamWaitEvent(s0, e_join, 0);

    {
        dim3 grid(M_ / WARPS_C, B_);
        gather_k<<<grid, 32 * WARPS_C, smem_g, s0>>>(centers_coords, out);
    }
}

// round 5
// speedup vs baseline: 2.4518x; 1.6356x over previous
#include <cuda_runtime.h>

#define B_    8
#define N_    8192
#define M_    2048
#define C_    64
#define K_    32
#define CH_   67
#define ROWW  68
#define GRID_ 10
#define CELLS_ 1000
#define HMAX  256

// Scratch (device globals — no allocation allowed)
__device__ float g_ptsT[B_ * N_ * ROWW];       // [b][n][68]
__device__ int   g_idx[B_ * M_ * K_];          // [b][m][32]
__device__ int   g_cellcnt[B_ * CELLS_];
__device__ int   g_cellstart[B_ * (CELLS_ + 1)];
__device__ int   g_cellcur[B_ * CELLS_];
__device__ float g_sx[B_ * N_], g_sy[B_ * N_], g_sz[B_ * N_];
__device__ int   g_sidx[B_ * N_];

__device__ __forceinline__ int cell1d(float v) {
    int c = (int)(v * 10.0f);
    return c > 9 ? 9 : (c < 0 ? 0 : c);
}

// ---------------------------------------------------------------------------
// Kernel A: pack + transpose (B,3,N)+(B,64,N) -> ptsT[b][n][67(+1)]
// ---------------------------------------------------------------------------
__global__ void __launch_bounds__(256) transpose_k(const float* __restrict__ pc,
                                                   const float* __restrict__ feat) {
    __shared__ float tile[CH_][33];
    int b  = blockIdx.y;
    int n0 = blockIdx.x * 32;
    int tx = threadIdx.x;
    int ty = threadIdx.y;

    for (int ch = ty; ch < CH_; ch += 8) {
        float v = (ch < 3)
            ? pc[((size_t)(b * 3 + ch)) * N_ + n0 + tx]
            : feat[((size_t)(b * C_ + (ch - 3))) * N_ + n0 + tx];
        tile[ch][tx] = v;
    }
    __syncthreads();

    for (int r = ty; r < 32; r += 8) {
        float* row = g_ptsT + (size_t)(b * N_ + n0 + r) * ROWW;
        row[tx]      = tile[tx][r];
        row[32 + tx] = tile[32 + tx][r];
        if (tx < 3) row[64 + tx] = tile[64 + tx][r];
    }
}

// ---------------------------------------------------------------------------
// Grid build: zero counts -> count -> scan -> scatter (cell-sorted points)
// ---------------------------------------------------------------------------
__global__ void zero_k() {
    g_cellcnt[blockIdx.x * CELLS_ + threadIdx.x] = 0;
}

__global__ void __launch_bounds__(256) count_k(const float* __restrict__ pc) {
    int b = blockIdx.y;
    int n = blockIdx.x * 256 + threadIdx.x;
    const float* P = pc + (size_t)b * 3 * N_;
    float x = P[n], y = P[N_ + n], z = P[2 * N_ + n];
    int cell = (cell1d(x) * 10 + cell1d(y)) * 10 + cell1d(z);
    atomicAdd(&g_cellcnt[b * CELLS_ + cell], 1);
}

__global__ void __launch_bounds__(1024) scan_k() {
    __shared__ int s[1024];
    int b = blockIdx.x;
    int t = threadIdx.x;
    int v = (t < CELLS_) ? g_cellcnt[b * CELLS_ + t] : 0;
    s[t] = v;
    __syncthreads();
    for (int off = 1; off < 1024; off <<= 1) {
        int u = (t >= off) ? s[t - off] : 0;
        __syncthreads();
        s[t] += u;
        __syncthreads();
    }
    if (t < CELLS_) {
        int excl = s[t] - v;
        g_cellstart[b * (CELLS_ + 1) + t] = excl;
        g_cellcur[b * CELLS_ + t] = excl;
    }
    if (t == CELLS_ - 1) g_cellstart[b * (CELLS_ + 1) + CELLS_] = s[t];
}

__global__ void __launch_bounds__(256) scatter_k(const float* __restrict__ pc) {
    int b = blockIdx.y;
    int n = blockIdx.x * 256 + threadIdx.x;
    const float* P = pc + (size_t)b * 3 * N_;
    float x = P[n], y = P[N_ + n], z = P[2 * N_ + n];
    int cell = (cell1d(x) * 10 + cell1d(y)) * 10 + cell1d(z);
    int pos = atomicAdd(&g_cellcur[b * CELLS_ + cell], 1);
    size_t o = (size_t)b * N_ + pos;
    g_sx[o] = x; g_sy[o] = y; g_sz[o] = z; g_sidx[o] = n;
}

// ---------------------------------------------------------------------------
// Selection: 32 smallest indices from per-warp hit buffer (unordered).
// R = register columns per lane (covers up to 32*R candidates).
// ---------------------------------------------------------------------------
template <int R>
__device__ __forceinline__ int select32(const int* __restrict__ hb, int cl,
                                        int cnt, int lane) {
    unsigned v[R];
    #pragma unroll
    for (int r = 0; r < R; r++) {
        int p = lane + 32 * r;
        v[r] = (p < cl) ? (unsigned)hb[p] : 0xffffffffu;
    }
    unsigned first = 0, kth = 0xffffffffu;
    #pragma unroll 1
    for (int it = 0; it < K_; it++) {
        unsigned lm = v[0];
        #pragma unroll
        for (int r = 1; r < R; r++) lm = min(lm, v[r]);
        unsigned mn = __reduce_min_sync(0xffffffffu, lm);
        if (mn == 0xffffffffu) break;   // exhausted (cnt < 32)
        if (it == 0) first = mn;
        if (it == lane) kth = mn;
        #pragma unroll
        for (int r = 0; r < R; r++) v[r] = (v[r] == mn) ? 0xffffffffu : v[r];
    }
    return (cnt == 0) ? 0 : ((lane < cnt) ? (int)kth : (int)first);
}

// ---------------------------------------------------------------------------
// Kernel B: grid ball query. One warp per center; scan 3x3x3 neighborhood
// (9 contiguous z-ranges). Exact hit test replicates reference numerics:
//   q, c2: rn mul/add chain;  dot: fma(cz,pz, fma(cy,py, cx*px))
//   d2 = (c2 + q) - (dot + dot);  hit = d2 < 0.01f
// ---------------------------------------------------------------------------
#define WARPS_Q 8
__global__ void __launch_bounds__(32 * WARPS_Q)
query_k(const float* __restrict__ cc) {
    __shared__ int hits[WARPS_Q][HMAX];
    int b    = blockIdx.y;
    int warp = threadIdx.x >> 5;
    int lane = threadIdx.x & 31;
    unsigned lmask_lt = (1u << lane) - 1u;
    int m = blockIdx.x * WARPS_Q + warp;
    int* hb = hits[warp];

    float cx = cc[(size_t)(b * 3 + 0) * M_ + m];
    float cy = cc[(size_t)(b * 3 + 1) * M_ + m];
    float cz = cc[(size_t)(b * 3 + 2) * M_ + m];
    float c2 = __fadd_rn(__fadd_rn(__fmul_rn(cx, cx), __fmul_rn(cy, cy)),
                         __fmul_rn(cz, cz));
    const float R2 = 0.01f;

    int icx = cell1d(cx), icy = cell1d(cy), icz = cell1d(cz);
    int zlo = icz > 0 ? icz - 1 : 0;
    int zhi = icz < 9 ? icz + 1 : 9;
    int xlo = icx > 0 ? icx - 1 : 0, xhi = icx < 9 ? icx + 1 : 9;
    int ylo = icy > 0 ? icy - 1 : 0, yhi = icy < 9 ? icy + 1 : 9;

    const int* cs = g_cellstart + b * (CELLS_ + 1);
    size_t bo = (size_t)b * N_;
    int cnt = 0;

    for (int dx = xlo; dx <= xhi; dx++) {
        for (int dy = ylo; dy <= yhi; dy++) {
            int base = (dx * 10 + dy) * 10;
            int s = cs[base + zlo];
            int e = cs[base + zhi + 1];
            for (int j0 = s; j0 < e; j0 += 32) {
                int j = j0 + lane;
                bool act = j < e;
                int jj = act ? j : s;
                float px = g_sx[bo + jj], py = g_sy[bo + jj], pz = g_sz[bo + jj];
                float q = __fadd_rn(__fadd_rn(__fmul_rn(px, px), __fmul_rn(py, py)),
                                    __fmul_rn(pz, pz));
                float dot = __fmaf_rn(cz, pz, __fmaf_rn(cy, py, __fmul_rn(cx, px)));
                float d2  = __fsub_rn(__fadd_rn(c2, q), __fadd_rn(dot, dot));
                bool hit = act && (d2 < R2);
                unsigned mask = __ballot_sync(0xffffffffu, hit);
                if (hit) {
                    int pos = cnt + __popc(mask & lmask_lt);
                    if (pos < HMAX) hb[pos] = g_sidx[bo + jj];
                }
                cnt += __popc(mask);
            }
        }
    }
    __syncwarp();

    int cl = cnt > HMAX ? HMAX : cnt;
    int res;
    if (cl <= 32)       res = select32<1>(hb, cl, cnt, lane);
    else if (cl <= 64)  res = select32<2>(hb, cl, cnt, lane);
    else if (cl <= 128) res = select32<4>(hb, cl, cnt, lane);
    else                res = select32<8>(hb, cl, cnt, lane);

    g_idx[((size_t)b * M_ + m) * K_ + lane] = res;
}

// ---------------------------------------------------------------------------
// Kernel C: gather. One warp per center; coalesced row reads from ptsT,
// per-warp shared transpose, coalesced output stores.
// ---------------------------------------------------------------------------
#define WARPS_C 8
__global__ void __launch_bounds__(32 * WARPS_C)
gather_k(const float* __restrict__ cc, float* __restrict__ out) {
    extern __shared__ float smc[];
    int b    = blockIdx.y;
    int warp = threadIdx.x >> 5;
    int lane = threadIdx.x & 31;
    int m = blockIdx.x * WARPS_C + warp;
    float* tile = smc + warp * (CH_ * 33);

    int my_i = g_idx[((size_t)b * M_ + m) * K_ + lane];

    #pragma unroll 8
    for (int j = 0; j < K_; j++) {
        int ij = __shfl_sync(0xffffffffu, my_i, j);
        const float* row = g_ptsT + (size_t)(b * N_ + ij) * ROWW;
        float v0 = row[lane];
        float v1 = row[32 + lane];
        tile[lane * 33 + j]        = v0;
        tile[(32 + lane) * 33 + j] = v1;
        if (lane < 3) tile[(64 + lane) * 33 + j] = row[64 + lane];
    }
    __syncwarp();

    float cx = cc[(size_t)(b * 3 + 0) * M_ + m];
    float cy = cc[(size_t)(b * 3 + 1) * M_ + m];
    float cz = cc[(size_t)(b * 3 + 2) * M_ + m];

    size_t obase = (((size_t)b * CH_) * M_ + m) * K_ + lane;
    const size_t cstride = (size_t)M_ * K_;
    out[obase + 0 * cstride] = __fsub_rn(tile[0 * 33 + lane], cx);
    out[obase + 1 * cstride] = __fsub_rn(tile[1 * 33 + lane], cy);
    out[obase + 2 * cstride] = __fsub_rn(tile[2 * 33 + lane], cz);
    #pragma unroll
    for (int c = 3; c < CH_; c++) {
        out[obase + (size_t)c * cstride] = tile[c * 33 + lane];
    }
}

// ---------------------------------------------------------------------------
extern "C" void kernel_launch(void* const* d_in, const int* in_sizes, int n_in,
                              void* d_out, int out_size) {
    const float* points_coords  = (const float*)d_in[0];   // (8, 3, 8192)
    const float* centers_coords = (const float*)d_in[1];   // (8, 3, 2048)
    const float* points_feats   = (const float*)d_in[2];   // (8, 64, 8192)
    float* out = (float*)d_out;                            // (8, 67, 2048, 32)

    const int smem_g = WARPS_C * CH_ * 33 * (int)sizeof(float);

    static bool init_done = false;
    static cudaStream_t s1;
    static cudaEvent_t e_fork, e_join;
    if (!init_done) {
        cudaFuncSetAttribute(gather_k, cudaFuncAttributeMaxDynamicSharedMemorySize, smem_g);
        cudaStreamCreateWithFlags(&s1, cudaStreamNonBlocking);
        cudaEventCreateWithFlags(&e_fork, cudaEventDisableTiming);
        cudaEventCreateWithFlags(&e_join, cudaEventDisableTiming);
        init_done = true;
    }

    cudaStream_t s0 = 0;

    // Fork: transpose on s1, grid-build + query on s0 (independent)
    cudaEventRecord(e_fork, s0);
    cudaStreamWaitEvent(s1, e_fork, 0);

    {
        dim3 grid(N_ / 32, B_);
        dim3 block(32, 8);
        transpose_k<<<grid, block, 0, s1>>>(points_coords, points_feats);
    }

    zero_k<<<B_, CELLS_, 0, s0>>>();
    {
        dim3 grid(N_ / 256, B_);
        count_k<<<grid, 256, 0, s0>>>(points_coords);
    }
    scan_k<<<B_, 1024, 0, s0>>>();
    {
        dim3 grid(N_ / 256, B_);
        scatter_k<<<grid, 256, 0, s0>>>(points_coords);
    }
    {
        dim3 grid(M_ / WARPS_Q, B_);
        query_k<<<grid, 32 * WARPS_Q, 0, s0>>>(centers_coords);
    }

    // Join: gather needs g_ptsT (s1) and g_idx (s0)
    cudaEventRecord(e_join, s1);
    cudaStreamWaitEvent(s0, e_join, 0);

    {
        dim3 grid(M_ / WARPS_C, B_);
        gather_k<<<grid, 32 * WARPS_C, smem_g, s0>>>(centers_coords, out);
    }
}

// round 6
// speedup vs baseline: 2.5270x; 1.0306x over previous
#include <cuda_runtime.h>

#define B_    8
#define N_    8192
#define M_    2048
#define C_    64
#define K_    32
#define CH_   67
#define ROWW  68
#define CELLS_ 1000
#define HMAX  256

// Scratch (device globals — no allocation allowed)
__device__ float  g_ptsT[B_ * N_ * ROWW];        // [b][n][68]
__device__ int    g_idx[B_ * M_ * K_];           // [b][m][32]
__device__ int    g_cellstart[B_ * (CELLS_ + 1)];
__device__ float4 g_pts4[B_ * N_];               // cell-sorted (x,y,z,idx-bits)

__device__ __forceinline__ int cell1d(float v) {
    int c = (int)(v * 10.0f);
    return c > 9 ? 9 : (c < 0 ? 0 : c);
}

// ---------------------------------------------------------------------------
// Kernel A: pack + transpose (B,3,N)+(B,64,N) -> ptsT[b][n][67(+1)]
// ---------------------------------------------------------------------------
__global__ void __launch_bounds__(256) transpose_k(const float* __restrict__ pc,
                                                   const float* __restrict__ feat) {
    __shared__ float tile[CH_][33];
    int b  = blockIdx.y;
    int n0 = blockIdx.x * 32;
    int tx = threadIdx.x;
    int ty = threadIdx.y;

    for (int ch = ty; ch < CH_; ch += 8) {
        float v = (ch < 3)
            ? pc[((size_t)(b * 3 + ch)) * N_ + n0 + tx]
            : feat[((size_t)(b * C_ + (ch - 3))) * N_ + n0 + tx];
        tile[ch][tx] = v;
    }
    __syncthreads();

    for (int r = ty; r < 32; r += 8) {
        float* row = g_ptsT + (size_t)(b * N_ + n0 + r) * ROWW;
        row[tx]      = tile[tx][r];
        row[32 + tx] = tile[32 + tx][r];
        if (tx < 3) row[64 + tx] = tile[64 + tx][r];
    }
}

// ---------------------------------------------------------------------------
// Fused grid build: one CTA per batch. count (smem atomics) -> two-level
// warp scan of 1000 cell counts -> scatter to cell-sorted float4 array.
// ---------------------------------------------------------------------------
#define PPT (N_ / 1024)   // points per thread = 8
__global__ void __launch_bounds__(1024) buildgrid_k(const float* __restrict__ pc) {
    __shared__ int scnt[CELLS_];
    __shared__ int scur[CELLS_];
    __shared__ int wsum[32];

    int b = blockIdx.x;
    int t = threadIdx.x;
    int lane = t & 31;
    int wid = t >> 5;

    for (int i = t; i < CELLS_; i += 1024) scnt[i] = 0;
    __syncthreads();

    const float* P = pc + (size_t)b * 3 * N_;
    float x[PPT], y[PPT], z[PPT];
    int cell[PPT];
    #pragma unroll
    for (int i = 0; i < PPT; i++) {
        int n = i * 1024 + t;
        x[i] = P[n]; y[i] = P[N_ + n]; z[i] = P[2 * N_ + n];
        cell[i] = (cell1d(x[i]) * 10 + cell1d(y[i])) * 10 + cell1d(z[i]);
        atomicAdd(&scnt[cell[i]], 1);
    }
    __syncthreads();

    // Two-level inclusive scan over 1024 slots (last 24 are zero)
    int v = (t < CELLS_) ? scnt[t] : 0;
    int val = v;
    #pragma unroll
    for (int o = 1; o < 32; o <<= 1) {
        int u = __shfl_up_sync(0xffffffffu, v, o);
        if (lane >= o) v += u;
    }
    if (lane == 31) wsum[wid] = v;
    __syncthreads();
    if (wid == 0) {
        int w = wsum[lane];
        #pragma unroll
        for (int o = 1; o < 32; o <<= 1) {
            int u = __shfl_up_sync(0xffffffffu, w, o);
            if (lane >= o) w += u;
        }
        wsum[lane] = w;
    }
    __syncthreads();
    int incl = v + (wid > 0 ? wsum[wid - 1] : 0);
    int excl = incl - val;
    if (t < CELLS_) {
        g_cellstart[b * (CELLS_ + 1) + t] = excl;
        scur[t] = excl;
    }
    if (t == CELLS_ - 1) g_cellstart[b * (CELLS_ + 1) + CELLS_] = incl;
    __syncthreads();

    size_t bo = (size_t)b * N_;
    #pragma unroll
    for (int i = 0; i < PPT; i++) {
        int n = i * 1024 + t;
        int pos = atomicAdd(&scur[cell[i]], 1);
        g_pts4[bo + pos] = make_float4(x[i], y[i], z[i], __int_as_float(n));
    }
}

// ---------------------------------------------------------------------------
// Selection: 32 smallest indices from per-warp hit buffer (unordered).
// ---------------------------------------------------------------------------
template <int R>
__device__ __forceinline__ int select32(const int* __restrict__ hb, int cl,
                                        int cnt, int lane) {
    unsigned v[R];
    #pragma unroll
    for (int r = 0; r < R; r++) {
        int p = lane + 32 * r;
        v[r] = (p < cl) ? (unsigned)hb[p] : 0xffffffffu;
    }
    unsigned first = 0, kth = 0xffffffffu;
    #pragma unroll 1
    for (int it = 0; it < K_; it++) {
        unsigned lm = v[0];
        #pragma unroll
        for (int r = 1; r < R; r++) lm = min(lm, v[r]);
        unsigned mn = __reduce_min_sync(0xffffffffu, lm);
        if (mn == 0xffffffffu) break;
        if (it == 0) first = mn;
        if (it == lane) kth = mn;
        #pragma unroll
        for (int r = 0; r < R; r++) v[r] = (v[r] == mn) ? 0xffffffffu : v[r];
    }
    return (cnt == 0) ? 0 : ((lane < cnt) ? (int)kth : (int)first);
}

// ---------------------------------------------------------------------------
// Kernel B: grid ball query. One warp per center; scan 3x3x3 neighborhood
// (9 contiguous z-ranges). Exact hit test replicates reference numerics.
// ---------------------------------------------------------------------------
#define WARPS_Q 8
__global__ void __launch_bounds__(32 * WARPS_Q)
query_k(const float* __restrict__ cc) {
    __shared__ int hits[WARPS_Q][HMAX];
    int b    = blockIdx.y;
    int warp = threadIdx.x >> 5;
    int lane = threadIdx.x & 31;
    unsigned lmask_lt = (1u << lane) - 1u;
    int m = blockIdx.x * WARPS_Q + warp;
    int* hb = hits[warp];

    float cx = cc[(size_t)(b * 3 + 0) * M_ + m];
    float cy = cc[(size_t)(b * 3 + 1) * M_ + m];
    float cz = cc[(size_t)(b * 3 + 2) * M_ + m];
    float c2 = __fadd_rn(__fadd_rn(__fmul_rn(cx, cx), __fmul_rn(cy, cy)),
                         __fmul_rn(cz, cz));
    const float R2 = 0.01f;

    int icx = cell1d(cx), icy = cell1d(cy), icz = cell1d(cz);
    int zlo = icz > 0 ? icz - 1 : 0;
    int zhi = icz < 9 ? icz + 1 : 9;
    int xlo = icx > 0 ? icx - 1 : 0, xhi = icx < 9 ? icx + 1 : 9;
    int ylo = icy > 0 ? icy - 1 : 0, yhi = icy < 9 ? icy + 1 : 9;

    const int* cs = g_cellstart + b * (CELLS_ + 1);
    size_t bo = (size_t)b * N_;
    int cnt = 0;

    for (int dx = xlo; dx <= xhi; dx++) {
        for (int dy = ylo; dy <= yhi; dy++) {
            int base = (dx * 10 + dy) * 10;
            int s = cs[base + zlo];
            int e = cs[base + zhi + 1];
            for (int j0 = s; j0 < e; j0 += 32) {
                int j = j0 + lane;
                bool act = j < e;
                float4 p = g_pts4[bo + (act ? j : s)];
                float q = __fadd_rn(__fadd_rn(__fmul_rn(p.x, p.x), __fmul_rn(p.y, p.y)),
                                    __fmul_rn(p.z, p.z));
                float dot = __fmaf_rn(cz, p.z, __fmaf_rn(cy, p.y, __fmul_rn(cx, p.x)));
                float d2  = __fsub_rn(__fadd_rn(c2, q), __fadd_rn(dot, dot));
                bool hit = act && (d2 < R2);
                unsigned mask = __ballot_sync(0xffffffffu, hit);
                if (hit) {
                    int pos = cnt + __popc(mask & lmask_lt);
                    if (pos < HMAX) hb[pos] = __float_as_int(p.w);
                }
                cnt += __popc(mask);
            }
        }
    }
    __syncwarp();

    int cl = cnt > HMAX ? HMAX : cnt;
    int res;
    if (cl <= 32)       res = select32<1>(hb, cl, cnt, lane);
    else if (cl <= 64)  res = select32<2>(hb, cl, cnt, lane);
    else if (cl <= 128) res = select32<4>(hb, cl, cnt, lane);
    else                res = select32<8>(hb, cl, cnt, lane);

    g_idx[((size_t)b * M_ + m) * K_ + lane] = res;
}

// ---------------------------------------------------------------------------
// Kernel C: gather. One warp per center; coalesced row reads from ptsT,
// per-warp shared transpose, coalesced output stores.
// ---------------------------------------------------------------------------
#define WARPS_C 8
__global__ void __launch_bounds__(32 * WARPS_C)
gather_k(const float* __restrict__ cc, float* __restrict__ out) {
    extern __shared__ float smc[];
    int b    = blockIdx.y;
    int warp = threadIdx.x >> 5;
    int lane = threadIdx.x & 31;
    int m = blockIdx.x * WARPS_C + warp;
    float* tile = smc + warp * (CH_ * 33);

    int my_i = g_idx[((size_t)b * M_ + m) * K_ + lane];

    #pragma unroll 8
    for (int j = 0; j < K_; j++) {
        int ij = __shfl_sync(0xffffffffu, my_i, j);
        const float* row = g_ptsT + (size_t)(b * N_ + ij) * ROWW;
        float v0 = row[lane];
        float v1 = row[32 + lane];
        tile[lane * 33 + j]        = v0;
        tile[(32 + lane) * 33 + j] = v1;
        if (lane < 3) tile[(64 + lane) * 33 + j] = row[64 + lane];
    }
    __syncwarp();

    float cx = cc[(size_t)(b * 3 + 0) * M_ + m];
    float cy = cc[(size_t)(b * 3 + 1) * M_ + m];
    float cz = cc[(size_t)(b * 3 + 2) * M_ + m];

    size_t obase = (((size_t)b * CH_) * M_ + m) * K_ + lane;
    const size_t cstride = (size_t)M_ * K_;
    out[obase + 0 * cstride] = __fsub_rn(tile[0 * 33 + lane], cx);
    out[obase + 1 * cstride] = __fsub_rn(tile[1 * 33 + lane], cy);
    out[obase + 2 * cstride] = __fsub_rn(tile[2 * 33 + lane], cz);
    #pragma unroll
    for (int c = 3; c < CH_; c++) {
        out[obase + (size_t)c * cstride] = tile[c * 33 + lane];
    }
}

// ---------------------------------------------------------------------------
extern "C" void kernel_launch(void* const* d_in, const int* in_sizes, int n_in,
                              void* d_out, int out_size) {
    const float* points_coords  = (const float*)d_in[0];   // (8, 3, 8192)
    const float* centers_coords = (const float*)d_in[1];   // (8, 3, 2048)
    const float* points_feats   = (const float*)d_in[2];   // (8, 64, 8192)
    float* out = (float*)d_out;                            // (8, 67, 2048, 32)

    const int smem_g = WARPS_C * CH_ * 33 * (int)sizeof(float);

    static bool init_done = false;
    static cudaStream_t s1;
    static cudaEvent_t e_fork, e_join;
    if (!init_done) {
        cudaFuncSetAttribute(gather_k, cudaFuncAttributeMaxDynamicSharedMemorySize, smem_g);
        cudaStreamCreateWithFlags(&s1, cudaStreamNonBlocking);
        cudaEventCreateWithFlags(&e_fork, cudaEventDisableTiming);
        cudaEventCreateWithFlags(&e_join, cudaEventDisableTiming);
        init_done = true;
    }

    cudaStream_t s0 = 0;

    // Fork: transpose on s1; grid build + query on s0 (independent)
    cudaEventRecord(e_fork, s0);
    cudaStreamWaitEvent(s1, e_fork, 0);

    {
        dim3 grid(N_ / 32, B_);
        dim3 block(32, 8);
        transpose_k<<<grid, block, 0, s1>>>(points_coords, points_feats);
    }

    buildgrid_k<<<B_, 1024, 0, s0>>>(points_coords);
    {
        dim3 grid(M_ / WARPS_Q, B_);
        query_k<<<grid, 32 * WARPS_Q, 0, s0>>>(centers_coords);
    }

    // Join: gather needs g_ptsT (s1) and g_idx (s0)
    cudaEventRecord(e_join, s1);
    cudaStreamWaitEvent(s0, e_join, 0);

    {
        dim3 grid(M_ / WARPS_C, B_);
        gather_k<<<grid, 32 * WARPS_C, smem_g, s0>>>(centers_coords, out);
    }
}